// round 8
// baseline (speedup 1.0000x reference)
#include <cuda_runtime.h>
#include <math_constants.h>

#define NUM_VIEW 300
#define NPAIR    150   // view pairs
#define WVIEW    80    // window: views scanned per point (covering-radius bound)
#define W0MAX    (NUM_VIEW - WVIEW)   // 220

// Interleaved paired codebook. Pair j (views 2j, 2j+1) occupies one 32B line:
//   g_pairs[2j]   = bits of {x0, x1, y0, y1}
//   g_pairs[2j+1] = bits of {z0, z1, c0, c1}   where c = -|v|^2/2
__device__ ulonglong2 g_pairs[2 * NPAIR];

__global__ void np_init_views_kernel() {
    int i = blockIdx.x * blockDim.x + threadIdx.x;
    if (i < NUM_VIEW) {
        // Match numpy float64 construction exactly, then cast to float32.
        double di  = (double)i;
        double zi  = (2.0 * di + 1.0) / (double)NUM_VIEW - 1.0;
        double r2  = 1.0 - zi * zi;
        if (r2 < 0.0) r2 = 0.0;
        double r   = sqrt(r2);
        const double PHI = (sqrt(5.0) - 1.0) * 0.5;
        double ang = 2.0 * di * CUDART_PI * PHI;
        double s, c;
        sincos(ang, &s, &c);
        float xf = (float)(r * c);
        float yf = (float)(r * s);
        float zf = (float)zi;
        float vv = __fadd_rn(__fadd_rn(__fmul_rn(xf, xf), __fmul_rn(yf, yf)),
                             __fmul_rn(zf, zf));
        float cf = -0.5f * vv;

        int j = i >> 1;
        int o = i & 1;
        float* fa = (float*)&g_pairs[2 * j];
        float* fb = (float*)&g_pairs[2 * j + 1];
        fa[0 + o] = xf;
        fa[2 + o] = yf;
        fb[0 + o] = zf;
        fb[2 + o] = cf;
    }
}

__device__ __forceinline__ unsigned long long np_fma2(
        unsigned long long a, unsigned long long b, unsigned long long c) {
    unsigned long long d;
    asm("fma.rn.f32x2 %0, %1, %2, %3;" : "=l"(d) : "l"(a), "l"(b), "l"(c));
    return d;
}

__device__ __forceinline__ unsigned long long np_pack2(float lo, float hi) {
    unsigned long long d;
    asm("mov.b64 %0, {%1, %2};" : "=l"(d) : "f"(lo), "f"(hi));
    return d;
}

__device__ __forceinline__ void np_unpack2(float& lo, float& hi,
                                           unsigned long long v) {
    asm("mov.b64 {%0, %1}, %2;" : "=f"(lo), "=f"(hi) : "l"(v));
}

__device__ __forceinline__ void np_merge_max(float& s0, int& i0, float s1, int i1) {
    // first-max (lowest index) wins on ties — matches argmin-first semantics
    bool g = (s1 > s0) || (s1 == s0 && i1 < i0);
    s0 = g ? s1 : s0;
    i0 = g ? i1 : i0;
}

// 2 threads per point. Views sorted by z -> winner lies within +-40 indices
// of i_c = round((u_z+1)*150). No shared memory: 4.8KB codebook is L1-resident.
// argmin(|n-v|^2) == argmax(dot(n,v) - |v|^2/2): packed f32x2 FMAs.
// MODE 0: indices written as float32 (output = 13*P floats)
// MODE 1: indices written as int64 bit-pattern (output = 14*P float slots)
template <int MODE>
__global__ void np_main_kernel(const float* __restrict__ normals,
                               const int*   __restrict__ idxs,
                               float*       __restrict__ out,
                               int N, int S, int logS, int P) {
    int t = blockIdx.x * blockDim.x + threadIdx.x;
    int p = t >> 1;
    int h = t & 1;
    int pc = (p < P) ? p : (P - 1);   // clamp, no divergence

    // gather loads issued first — overlap with init kernel via PDL
    int b   = (logS >= 0) ? (pc >> logS) : (pc / S);
    int idx = idxs[pc];
    const float* nptr = normals + ((long long)b * N + idx) * 3;
    float nx = __ldg(nptr + 0);
    float ny = __ldg(nptr + 1);
    float nz = __ldg(nptr + 2);

    // wait for init kernel's codebook writes (PDL dependency)
#if __CUDA_ARCH__ >= 900
    cudaGridDependencySynchronize();
#endif

    // window center from normalized z (approximation fine: 1.4x margin)
    float nn  = fmaf(nx, nx, fmaf(ny, ny, nz * nz));
    float uz  = nz * rsqrtf(nn);
    int   ic  = __float2int_rn(fmaf(uz, 150.0f, 150.0f));
    int   w0  = ic - (WVIEW / 2);
    w0 = (w0 < 0) ? 0 : ((w0 > W0MAX) ? W0MAX : w0);
    w0 &= ~1;                 // even start so pairs align
    int jp = w0 >> 1;         // first window pair

    unsigned long long pnx = np_pack2(nx, nx);
    unsigned long long pny = np_pack2(ny, ny);
    unsigned long long pnz = np_pack2(nz, nz);

    // --- argmax over this lane's 20 window pairs: 2 pairs/iter, 10 iters ---
    float bAl = -CUDART_INF_F, bAh = -CUDART_INF_F,
          bBl = -CUDART_INF_F, bBh = -CUDART_INF_F;
    int   mAl = 0, mAh = 0, mBl = 0, mBh = 0;

#pragma unroll 5
    for (int m = 0; m < 10; m++) {
        int jA = jp + 2 * m + h;
        int jB = jA + 20;
        ulonglong2 A0 = __ldg(&g_pairs[2 * jA]);
        ulonglong2 B0 = __ldg(&g_pairs[2 * jA + 1]);
        ulonglong2 A1 = __ldg(&g_pairs[2 * jB]);
        ulonglong2 B1 = __ldg(&g_pairs[2 * jB + 1]);

        unsigned long long s0 = np_fma2(pnx, A0.x,
                                 np_fma2(pny, A0.y, np_fma2(pnz, B0.x, B0.y)));
        unsigned long long s1 = np_fma2(pnx, A1.x,
                                 np_fma2(pny, A1.y, np_fma2(pnz, B1.x, B1.y)));

        float f0l, f0h, f1l, f1h;
        np_unpack2(f0l, f0h, s0);
        np_unpack2(f1l, f1h, s1);

        // strict > keeps first-win; ternary form -> SEL (4-cyc) chains
        bool gAl = f0l > bAl;  bAl = gAl ? f0l : bAl;  mAl = gAl ? m : mAl;
        bool gAh = f0h > bAh;  bAh = gAh ? f0h : bAh;  mAh = gAh ? m : mAh;
        bool gBl = f1l > bBl;  bBl = gBl ? f1l : bBl;  mBl = gBl ? m : mBl;
        bool gBh = f1h > bBh;  bBh = gBh ? f1h : bBh;  mBh = gBh ? m : mBh;
    }

    // reconstruct global view indices
    int iAl = 2 * (jp + 2 * mAl + h);
    int iAh = 2 * (jp + 2 * mAh + h) + 1;
    int iBl = 2 * (jp + 2 * mBl + h + 20);
    int iBh = 2 * (jp + 2 * mBh + h + 20) + 1;

    // merge 4 accumulators (index tie-break keeps exact first-win semantics)
    np_merge_max(bAl, iAl, bAh, iAh);
    np_merge_max(bBl, iBl, bBh, iBh);
    np_merge_max(bAl, iAl, bBl, iBl);

    // merge across the lane pair
    float os = __shfl_xor_sync(0xffffffffu, bAl, 1);
    int   oi = __shfl_xor_sync(0xffffffffu, iAl, 1);
    np_merge_max(bAl, iAl, os, oi);
    int bi = iAl;

    // --- rotation matrix from towards = -n, angle = 0 (R1 = I, rot = R2) ---
    float ax_x = -nx, ax_y = -ny, ax_z = -nz;
    float ay_x = -ax_y;   // = ny
    float ay_y =  ax_x;   // = -nx
    float ay_z = 0.0f;
    if (ay_x * ay_x + ay_y * ay_y + ay_z * ay_z == 0.0f) {
        ay_x = 0.0f; ay_y = 1.0f; ay_z = 0.0f;
    }
    float inva = 1.0f / sqrtf(ax_x * ax_x + ax_y * ax_y + ax_z * ax_z);
    ax_x *= inva; ax_y *= inva; ax_z *= inva;
    float invy = 1.0f / sqrtf(ay_x * ay_x + ay_y * ay_y + ay_z * ay_z);
    ay_x *= invy; ay_y *= invy; ay_z *= invy;
    float az_x = ax_y * ay_z - ax_z * ay_y;
    float az_y = ax_z * ay_x - ax_x * ay_z;
    float az_z = ax_x * ay_y - ax_y * ay_x;

    // --- outputs (stores split between the two lanes of the pair) ---
    if (p < P) {
        float* out_xyz;
        float* out_rot;
        if (MODE == 0) {
            out_xyz = out + P;
            out_rot = out + P + 3 * (long long)P;
        } else {
            out_xyz = out + 2 * (long long)P;
            out_rot = out + 2 * (long long)P + 3 * (long long)P;
        }

        long long base3 = (long long)p * 3;
        long long base9 = (long long)p * 9;

        if (h == 0) {
            if (MODE == 0) {
                out[p] = (float)bi;
            } else {
                ((long long*)out)[p] = (long long)bi;
            }
            out_xyz[base3 + 0] = nx;
            out_xyz[base3 + 1] = ny;
            out_xyz[base3 + 2] = nz;
            // row-major [r][c]: col0 = ax, col1 = ay, col2 = az
            out_rot[base9 + 0] = ax_x;
            out_rot[base9 + 1] = ay_x;
            out_rot[base9 + 2] = az_x;
            out_rot[base9 + 3] = ax_y;
        } else {
            out_rot[base9 + 4] = ay_y;
            out_rot[base9 + 5] = az_y;
            out_rot[base9 + 6] = ax_z;
            out_rot[base9 + 7] = ay_z;
            out_rot[base9 + 8] = az_z;
        }
    }
}

extern "C" void kernel_launch(void* const* d_in, const int* in_sizes, int n_in,
                              void* d_out, int out_size) {
    const float* normals = (const float*)d_in[0];
    const int*   idxs    = (const int*)d_in[1];
    float*       out     = (float*)d_out;

    const int B = 8;
    int P = in_sizes[1];            // B*S = 32768
    int S = P / B;                  // 4096
    int N = in_sizes[0] / (B * 3);  // 500000

    int logS = -1;
    if (S > 0 && (S & (S - 1)) == 0) {
        logS = 0;
        while ((1 << logS) < S) logS++;
    }

    np_init_views_kernel<<<75, 4>>>();

    // 2 lanes per point; one balanced wave: 147 blocks x 448 threads
    const int threads = 448;
    long long total = 2LL * P;
    int blocks = (int)((total + threads - 1) / threads);

    // PDL: main may launch before init completes; it gates on
    // cudaGridDependencySynchronize() before reading the codebook.
    cudaLaunchConfig_t cfg = {};
    cfg.gridDim  = dim3((unsigned)blocks, 1, 1);
    cfg.blockDim = dim3((unsigned)threads, 1, 1);
    cfg.dynamicSmemBytes = 0;
    cfg.stream = 0;
    cudaLaunchAttribute attrs[1];
    attrs[0].id = cudaLaunchAttributeProgrammaticStreamSerialization;
    attrs[0].val.programmaticStreamSerializationAllowed = 1;
    cfg.attrs = attrs;
    cfg.numAttrs = 1;

    if (out_size == 14 * P) {
        cudaLaunchKernelEx(&cfg, np_main_kernel<1>,
                           normals, idxs, out, N, S, logS, P);
    } else {
        cudaLaunchKernelEx(&cfg, np_main_kernel<0>,
                           normals, idxs, out, N, S, logS, P);
    }
}

// round 9
// speedup vs baseline: 1.1831x; 1.1831x over previous
#include <cuda_runtime.h>
#include <math_constants.h>
#include <math.h>

#define NUM_VIEW 300
#define NPAIR    150   // view pairs
#define WVIEW    80    // window: views scanned per point (covering-radius bound)
#define W0MAX    (NUM_VIEW - WVIEW)   // 220
#define TPB      448   // threads per block
#define PPB      224   // points per block (2 lanes/point)

// Codebook passed BY VALUE as a kernel parameter (4.8KB, constant bank).
// Pair j (views 2j, 2j+1):
//   A[j] = bits of {x0, x1, y0, y1}
//   B[j] = bits of {z0, z1, c0, c1}   where c = -|v|^2/2
struct NPCodebook {
    ulonglong2 A[NPAIR];
    ulonglong2 B[NPAIR];
};

__device__ __forceinline__ unsigned long long np_fma2(
        unsigned long long a, unsigned long long b, unsigned long long c) {
    unsigned long long d;
    asm("fma.rn.f32x2 %0, %1, %2, %3;" : "=l"(d) : "l"(a), "l"(b), "l"(c));
    return d;
}

__device__ __forceinline__ unsigned long long np_pack2(float lo, float hi) {
    unsigned long long d;
    asm("mov.b64 %0, {%1, %2};" : "=l"(d) : "f"(lo), "f"(hi));
    return d;
}

__device__ __forceinline__ void np_unpack2(float& lo, float& hi,
                                           unsigned long long v) {
    asm("mov.b64 {%0, %1}, %2;" : "=f"(lo), "=f"(hi) : "l"(v));
}

__device__ __forceinline__ void np_merge_max(float& s0, int& i0, float s1, int i1) {
    // first-max (lowest index) wins on ties — matches argmin-first semantics
    bool g = (s1 > s0) || (s1 == s0 && i1 < i0);
    s0 = g ? s1 : s0;
    i0 = g ? i1 : i0;
}

// 2 threads per point. Views sorted by z -> winner lies within +-40 indices
// of i_c = round((u_z+1)*150). Codebook: kernel param -> smem. Outputs staged
// in smem, then block-coalesced float4 copy-out.
// argmin(|n-v|^2) == argmax(dot(n,v) - |v|^2/2): packed f32x2 FMAs.
// MODE 0: indices written as float32 (output = 13*P floats)
// MODE 1: indices written as int64 bit-pattern (output = 14*P float slots)
template <int MODE>
__global__ void __launch_bounds__(TPB)
np_main_kernel(const __grid_constant__ NPCodebook cb,
               const float* __restrict__ normals,
               const int*   __restrict__ idxs,
               float*       __restrict__ out,
               int N, int S, int logS, int P) {
    __shared__ ulonglong2 sA[NPAIR];
    __shared__ ulonglong2 sB[NPAIR];
    __shared__ __align__(16) float sROT[PPB * 9];
    __shared__ __align__(16) float sXYZ[PPB * 3];
    __shared__ __align__(16) unsigned long long sIND[PPB];

    int tid = threadIdx.x;
    int t   = blockIdx.x * TPB + tid;
    int p   = t >> 1;
    int h   = t & 1;
    int lp  = tid >> 1;               // local pair index 0..223
    int pc  = (p < P) ? p : (P - 1);  // clamp, keep barriers convergent

    // gather loads issued first — overlap with codebook preload
    int b   = (logS >= 0) ? (pc >> logS) : (pc / S);
    int idx = idxs[pc];
    const float* nptr = normals + ((long long)b * N + idx) * 3;
    float nx = __ldg(nptr + 0);
    float ny = __ldg(nptr + 1);
    float nz = __ldg(nptr + 2);

    // codebook param (constant bank) -> shared
    for (int i = tid; i < NPAIR; i += TPB) {
        sA[i] = cb.A[i];
        sB[i] = cb.B[i];
    }
    __syncthreads();

    // window center from normalized z (approximation fine: 1.4x margin)
    float nn  = fmaf(nx, nx, fmaf(ny, ny, nz * nz));
    float uz  = nz * rsqrtf(nn);
    int   ic  = __float2int_rn(fmaf(uz, 150.0f, 150.0f));
    int   w0  = ic - (WVIEW / 2);
    w0 = (w0 < 0) ? 0 : ((w0 > W0MAX) ? W0MAX : w0);
    w0 &= ~1;                 // even start so pairs align
    int jp = w0 >> 1;         // first window pair

    unsigned long long pnx = np_pack2(nx, nx);
    unsigned long long pny = np_pack2(ny, ny);
    unsigned long long pnz = np_pack2(nz, nz);

    // --- argmax over this lane's 20 window pairs: 2 pairs/iter, 10 iters ---
    float bAl = -CUDART_INF_F, bAh = -CUDART_INF_F,
          bBl = -CUDART_INF_F, bBh = -CUDART_INF_F;
    int   mAl = 0, mAh = 0, mBl = 0, mBh = 0;

#pragma unroll
    for (int m = 0; m < 10; m++) {
        int jA = jp + 2 * m + h;
        int jB = jA + 20;
        ulonglong2 A0 = sA[jA], B0 = sB[jA];
        ulonglong2 A1 = sA[jB], B1 = sB[jB];

        unsigned long long s0 = np_fma2(pnx, A0.x,
                                 np_fma2(pny, A0.y, np_fma2(pnz, B0.x, B0.y)));
        unsigned long long s1 = np_fma2(pnx, A1.x,
                                 np_fma2(pny, A1.y, np_fma2(pnz, B1.x, B1.y)));

        float f0l, f0h, f1l, f1h;
        np_unpack2(f0l, f0h, s0);
        np_unpack2(f1l, f1h, s1);

        // strict > keeps first-win; ternary form -> SEL (4-cyc) chains
        bool gAl = f0l > bAl;  bAl = gAl ? f0l : bAl;  mAl = gAl ? m : mAl;
        bool gAh = f0h > bAh;  bAh = gAh ? f0h : bAh;  mAh = gAh ? m : mAh;
        bool gBl = f1l > bBl;  bBl = gBl ? f1l : bBl;  mBl = gBl ? m : mBl;
        bool gBh = f1h > bBh;  bBh = gBh ? f1h : bBh;  mBh = gBh ? m : mBh;
    }

    // reconstruct global view indices
    int iAl = 2 * (jp + 2 * mAl + h);
    int iAh = 2 * (jp + 2 * mAh + h) + 1;
    int iBl = 2 * (jp + 2 * mBl + h + 20);
    int iBh = 2 * (jp + 2 * mBh + h + 20) + 1;

    // merge 4 accumulators (index tie-break keeps exact first-win semantics)
    np_merge_max(bAl, iAl, bAh, iAh);
    np_merge_max(bBl, iBl, bBh, iBh);
    np_merge_max(bAl, iAl, bBl, iBl);

    // merge across the lane pair
    float os = __shfl_xor_sync(0xffffffffu, bAl, 1);
    int   oi = __shfl_xor_sync(0xffffffffu, iAl, 1);
    np_merge_max(bAl, iAl, os, oi);
    int bi = iAl;

    // --- rotation matrix from towards = -n, angle = 0 (R1 = I, rot = R2) ---
    float ax_x = -nx, ax_y = -ny, ax_z = -nz;
    float ay_x = -ax_y;   // = ny
    float ay_y =  ax_x;   // = -nx
    float ay_z = 0.0f;
    if (ay_x * ay_x + ay_y * ay_y + ay_z * ay_z == 0.0f) {
        ay_x = 0.0f; ay_y = 1.0f; ay_z = 0.0f;
    }
    float inva = 1.0f / sqrtf(ax_x * ax_x + ax_y * ax_y + ax_z * ax_z);
    ax_x *= inva; ax_y *= inva; ax_z *= inva;
    float invy = 1.0f / sqrtf(ay_x * ay_x + ay_y * ay_y + ay_z * ay_z);
    ay_x *= invy; ay_y *= invy; ay_z *= invy;
    float az_x = ax_y * ay_z - ax_z * ay_y;
    float az_y = ax_z * ay_x - ax_x * ay_z;
    float az_z = ax_x * ay_y - ax_y * ay_x;

    // --- stage results in shared (garbage for clamped p>=P is never copied) ---
    float* rotp = sROT + lp * 9;
    if (h == 0) {
        if (MODE == 0) {
            ((float*)sIND)[lp] = (float)bi;
        } else {
            sIND[lp] = (unsigned long long)(long long)bi;
        }
        sXYZ[lp * 3 + 0] = nx;
        sXYZ[lp * 3 + 1] = ny;
        sXYZ[lp * 3 + 2] = nz;
        // row-major [r][c]: col0 = ax, col1 = ay, col2 = az
        rotp[0] = ax_x;
        rotp[1] = ay_x;
        rotp[2] = az_x;
        rotp[3] = ax_y;
    } else {
        rotp[4] = ay_y;
        rotp[5] = az_y;
        rotp[6] = ax_z;
        rotp[7] = ay_z;
        rotp[8] = az_z;
    }
    __syncthreads();

    // --- block-coalesced copy-out ---
    int p0 = blockIdx.x * PPB;
    int nvalid = P - p0;
    if (nvalid > PPB) nvalid = PPB;
    if (nvalid <= 0) return;

    float* out_xyz;
    float* out_rot;
    if (MODE == 0) {
        out_xyz = out + P;
        out_rot = out + P + 3 * (long long)P;
    } else {
        out_xyz = out + 2 * (long long)P;
        out_rot = out + 2 * (long long)P + 3 * (long long)P;
    }

    // rot: nvalid*9 floats
    {
        float* g = out_rot + (long long)p0 * 9;
        int cnt = nvalid * 9;
        int cnt4 = cnt >> 2;
        for (int i = tid; i < cnt4; i += TPB)
            ((float4*)g)[i] = ((const float4*)sROT)[i];
        for (int i = (cnt4 << 2) + tid; i < cnt; i += TPB)
            g[i] = sROT[i];
    }
    // xyz: nvalid*3 floats
    {
        float* g = out_xyz + (long long)p0 * 3;
        int cnt = nvalid * 3;
        int cnt4 = cnt >> 2;
        for (int i = tid; i < cnt4; i += TPB)
            ((float4*)g)[i] = ((const float4*)sXYZ)[i];
        for (int i = (cnt4 << 2) + tid; i < cnt; i += TPB)
            g[i] = sXYZ[i];
    }
    // indices
    if (MODE == 0) {
        float* g = out + p0;
        const float* s = (const float*)sIND;
        int cnt4 = nvalid >> 2;
        for (int i = tid; i < cnt4; i += TPB)
            ((float4*)g)[i] = ((const float4*)s)[i];
        for (int i = (cnt4 << 2) + tid; i < nvalid; i += TPB)
            g[i] = s[i];
    } else {
        unsigned long long* g = (unsigned long long*)out + p0;
        int cnt2 = nvalid >> 1;
        for (int i = tid; i < cnt2; i += TPB)
            ((ulonglong2*)g)[i] = ((const ulonglong2*)sIND)[i];
        for (int i = (cnt2 << 1) + tid; i < nvalid; i += TPB)
            g[i] = sIND[i];
    }
}

// Host-side codebook build. glibc fp64 sin/cos/sqrt matches numpy's float64
// libm dispatch on this host; volatile blocks FMA contraction so the fp32
// sum-of-squares matches jnp.sum(views*views) rounding.
static void np_build_codebook(NPCodebook* cb) {
    const double PHI = (sqrt(5.0) - 1.0) * 0.5;
    for (int i = 0; i < NUM_VIEW; i++) {
        double di = (double)i;
        double zi = (2.0 * di + 1.0) / (double)NUM_VIEW - 1.0;
        double r2 = 1.0 - zi * zi;
        if (r2 < 0.0) r2 = 0.0;
        double r  = sqrt(r2);
        double ang = 2.0 * di * M_PI * PHI;
        volatile float xf = (float)(r * cos(ang));
        volatile float yf = (float)(r * sin(ang));
        volatile float zf = (float)zi;
        volatile float xx = xf * xf;
        volatile float yy = yf * yf;
        volatile float zz = zf * zf;
        volatile float s1 = xx + yy;
        volatile float vv = s1 + zz;
        float cf = -0.5f * (float)vv;

        int j = i >> 1;
        int o = i & 1;
        float* fa = (float*)&cb->A[j];
        float* fb = (float*)&cb->B[j];
        fa[0 + o] = xf;
        fa[2 + o] = yf;
        fb[0 + o] = zf;
        fb[2 + o] = cf;
    }
}

extern "C" void kernel_launch(void* const* d_in, const int* in_sizes, int n_in,
                              void* d_out, int out_size) {
    const float* normals = (const float*)d_in[0];
    const int*   idxs    = (const int*)d_in[1];
    float*       out     = (float*)d_out;

    const int B = 8;
    int P = in_sizes[1];            // B*S = 32768
    int S = P / B;                  // 4096
    int N = in_sizes[0] / (B * 3);  // 500000

    int logS = -1;
    if (S > 0 && (S & (S - 1)) == 0) {
        logS = 0;
        while ((1 << logS) < S) logS++;
    }

    NPCodebook cb;
    np_build_codebook(&cb);

    // 2 lanes per point; single kernel, one balanced wave: 147 x 448
    long long total = 2LL * P;
    int blocks = (int)((total + TPB - 1) / TPB);
    if (out_size == 14 * P) {
        np_main_kernel<1><<<blocks, TPB>>>(cb, normals, idxs, out, N, S, logS, P);
    } else {
        np_main_kernel<0><<<blocks, TPB>>>(cb, normals, idxs, out, N, S, logS, P);
    }
}

// round 10
// speedup vs baseline: 1.4963x; 1.2647x over previous
#include <cuda_runtime.h>
#include <math_constants.h>
#include <math.h>

#define NUM_VIEW 300
#define NPAIR    150   // view pairs
#define WVIEW    80    // window: views scanned per point (covering-radius bound)
#define W0MAX    (NUM_VIEW - WVIEW)   // 220
#define TPB      448   // threads per block

// Codebook passed BY VALUE as a kernel parameter (2.4KB, constant bank).
// Pair j (views 2j, 2j+1):  A[j] = bits of {x0, x1, y0, y1}
// z is analytic (z_i = (2i+1)/300 - 1) and the -|v|^2/2 term is an
// argmax-invariant constant (up to ~1e-7), so only x,y are stored.
struct NPCodebook {
    ulonglong2 A[NPAIR];
};

__device__ __forceinline__ unsigned long long np_fma2(
        unsigned long long a, unsigned long long b, unsigned long long c) {
    unsigned long long d;
    asm("fma.rn.f32x2 %0, %1, %2, %3;" : "=l"(d) : "l"(a), "l"(b), "l"(c));
    return d;
}

__device__ __forceinline__ unsigned long long np_add2(
        unsigned long long a, unsigned long long b) {
    unsigned long long d;
    asm("add.rn.f32x2 %0, %1, %2;" : "=l"(d) : "l"(a), "l"(b));
    return d;
}

__device__ __forceinline__ unsigned long long np_pack2(float lo, float hi) {
    unsigned long long d;
    asm("mov.b64 %0, {%1, %2};" : "=l"(d) : "f"(lo), "f"(hi));
    return d;
}

__device__ __forceinline__ void np_unpack2(float& lo, float& hi,
                                           unsigned long long v) {
    asm("mov.b64 {%0, %1}, %2;" : "=f"(lo), "=f"(hi) : "l"(v));
}

__device__ __forceinline__ void np_merge_max(float& s0, int& i0, float s1, int i1) {
    // first-max (lowest index) wins on ties — matches argmin-first semantics
    bool g = (s1 > s0) || (s1 == s0 && i1 < i0);
    s0 = g ? s1 : s0;
    i0 = g ? i1 : i0;
}

// 2 threads per point. Views sorted by z -> winner lies within +-40 indices
// of i_c = round((u_z+1)*150). Codebook xy: kernel param -> smem (2.4KB);
// z-term carried analytically in a packed register (no load).
// argmin(|n-v|^2) == argmax(dot(n,v) - |v|^2/2) == argmax(dot(n,v)) + eps.
// MODE 0: indices written as float32 (output = 13*P floats)
// MODE 1: indices written as int64 bit-pattern (output = 14*P float slots)
template <int MODE>
__global__ void __launch_bounds__(TPB)
np_main_kernel(const __grid_constant__ NPCodebook cb,
               const float* __restrict__ normals,
               const int*   __restrict__ idxs,
               float*       __restrict__ out,
               int N, int S, int logS, int P) {
    __shared__ ulonglong2 sA[NPAIR];

    int tid = threadIdx.x;
    int t   = blockIdx.x * TPB + tid;
    int p   = t >> 1;
    int h   = t & 1;
    int pc  = (p < P) ? p : (P - 1);  // clamp, keep barrier convergent

    // gather loads issued first — overlap with codebook preload
    int b   = (logS >= 0) ? (pc >> logS) : (pc / S);
    int idx = idxs[pc];
    const float* nptr = normals + ((long long)b * N + idx) * 3;
    float nx = __ldg(nptr + 0);
    float ny = __ldg(nptr + 1);
    float nz = __ldg(nptr + 2);

    // codebook param (constant bank) -> shared
    for (int i = tid; i < NPAIR; i += TPB)
        sA[i] = cb.A[i];
    __syncthreads();

    // window center from normalized z (approximation fine: 1.4x margin)
    float nn  = fmaf(nx, nx, fmaf(ny, ny, nz * nz));
    float uz  = nz * rsqrtf(nn);
    int   ic  = __float2int_rn(fmaf(uz, 150.0f, 150.0f));
    int   w0  = ic - (WVIEW / 2);
    w0 = (w0 < 0) ? 0 : ((w0 > W0MAX) ? W0MAX : w0);
    w0 &= ~1;                 // even start so pairs align
    int jp = w0 >> 1;         // first window pair

    unsigned long long pnx = np_pack2(nx, nx);
    unsigned long long pny = np_pack2(ny, ny);

    // analytic z-terms: views in pair j are i = 2j (lo), 2j+1 (hi);
    // z_i = (2i+1)/300 - 1. Per unroll step j += 2 -> views += 4 -> dz = 8/300.
    const float inv300 = 1.0f / 300.0f;
    int jA0 = jp + h;
    float zAlo = fmaf((float)(4 * jA0 + 1), inv300, -1.0f);
    float zAhi = zAlo + 2.0f * inv300;
    unsigned long long pzA = np_pack2(nz * zAlo, nz * zAhi);
    float zstep = nz * (80.0f * inv300);   // jB = jA + 20 -> views +40
    unsigned long long pzB = np_add2(pzA, np_pack2(zstep, zstep));
    float dzf = nz * (8.0f * inv300);
    unsigned long long dpz = np_pack2(dzf, dzf);

    // --- argmax over this lane's 20 window pairs: 2 pairs/iter, 10 iters ---
    float bAl = -CUDART_INF_F, bAh = -CUDART_INF_F,
          bBl = -CUDART_INF_F, bBh = -CUDART_INF_F;
    int   mAl = 0, mAh = 0, mBl = 0, mBh = 0;

#pragma unroll
    for (int m = 0; m < 10; m++) {
        int jA = jp + 2 * m + h;
        int jB = jA + 20;
        ulonglong2 A0 = sA[jA];
        ulonglong2 A1 = sA[jB];

        unsigned long long s0 = np_fma2(pnx, A0.x, np_fma2(pny, A0.y, pzA));
        unsigned long long s1 = np_fma2(pnx, A1.x, np_fma2(pny, A1.y, pzB));
        pzA = np_add2(pzA, dpz);
        pzB = np_add2(pzB, dpz);

        float f0l, f0h, f1l, f1h;
        np_unpack2(f0l, f0h, s0);
        np_unpack2(f1l, f1h, s1);

        // strict > keeps first-win; ternary form -> SEL (4-cyc) chains
        bool gAl = f0l > bAl;  bAl = gAl ? f0l : bAl;  mAl = gAl ? m : mAl;
        bool gAh = f0h > bAh;  bAh = gAh ? f0h : bAh;  mAh = gAh ? m : mAh;
        bool gBl = f1l > bBl;  bBl = gBl ? f1l : bBl;  mBl = gBl ? m : mBl;
        bool gBh = f1h > bBh;  bBh = gBh ? f1h : bBh;  mBh = gBh ? m : mBh;
    }

    // reconstruct global view indices
    int iAl = 2 * (jp + 2 * mAl + h);
    int iAh = 2 * (jp + 2 * mAh + h) + 1;
    int iBl = 2 * (jp + 2 * mBl + h + 20);
    int iBh = 2 * (jp + 2 * mBh + h + 20) + 1;

    // merge 4 accumulators (index tie-break keeps exact first-win semantics)
    np_merge_max(bAl, iAl, bAh, iAh);
    np_merge_max(bBl, iBl, bBh, iBh);
    np_merge_max(bAl, iAl, bBl, iBl);

    // merge across the lane pair
    float os = __shfl_xor_sync(0xffffffffu, bAl, 1);
    int   oi = __shfl_xor_sync(0xffffffffu, iAl, 1);
    np_merge_max(bAl, iAl, os, oi);
    int bi = iAl;

    // --- rotation matrix from towards = -n, angle = 0 (R1 = I, rot = R2) ---
    float ax_x = -nx, ax_y = -ny, ax_z = -nz;
    float ay_x = -ax_y;   // = ny
    float ay_y =  ax_x;   // = -nx
    float ay_z = 0.0f;
    if (ay_x * ay_x + ay_y * ay_y + ay_z * ay_z == 0.0f) {
        ay_x = 0.0f; ay_y = 1.0f; ay_z = 0.0f;
    }
    float inva = 1.0f / sqrtf(ax_x * ax_x + ax_y * ax_y + ax_z * ax_z);
    ax_x *= inva; ax_y *= inva; ax_z *= inva;
    float invy = 1.0f / sqrtf(ay_x * ay_x + ay_y * ay_y + ay_z * ay_z);
    ay_x *= invy; ay_y *= invy; ay_z *= invy;
    float az_x = ax_y * ay_z - ax_z * ay_y;
    float az_y = ax_z * ay_x - ax_x * ay_z;
    float az_z = ax_x * ay_y - ax_y * ay_x;

    // --- outputs (stores split between the two lanes of the pair) ---
    if (p < P) {
        float* out_xyz;
        float* out_rot;
        if (MODE == 0) {
            out_xyz = out + P;
            out_rot = out + P + 3 * (long long)P;
        } else {
            out_xyz = out + 2 * (long long)P;
            out_rot = out + 2 * (long long)P + 3 * (long long)P;
        }

        long long base3 = (long long)p * 3;
        long long base9 = (long long)p * 9;

        if (h == 0) {
            if (MODE == 0) {
                out[p] = (float)bi;
            } else {
                ((long long*)out)[p] = (long long)bi;
            }
            out_xyz[base3 + 0] = nx;
            out_xyz[base3 + 1] = ny;
            out_xyz[base3 + 2] = nz;
            // row-major [r][c]: col0 = ax, col1 = ay, col2 = az
            out_rot[base9 + 0] = ax_x;
            out_rot[base9 + 1] = ay_x;
            out_rot[base9 + 2] = az_x;
            out_rot[base9 + 3] = ax_y;
        } else {
            out_rot[base9 + 4] = ay_y;
            out_rot[base9 + 5] = az_y;
            out_rot[base9 + 6] = ax_z;
            out_rot[base9 + 7] = ay_z;
            out_rot[base9 + 8] = az_z;
        }
    }
}

// Host-side codebook build (fp64 libm matches numpy's float64 path).
static void np_build_codebook(NPCodebook* cb) {
    const double PHI = (sqrt(5.0) - 1.0) * 0.5;
    for (int i = 0; i < NUM_VIEW; i++) {
        double di = (double)i;
        double zi = (2.0 * di + 1.0) / (double)NUM_VIEW - 1.0;
        double r2 = 1.0 - zi * zi;
        if (r2 < 0.0) r2 = 0.0;
        double r  = sqrt(r2);
        double ang = 2.0 * di * M_PI * PHI;
        float xf = (float)(r * cos(ang));
        float yf = (float)(r * sin(ang));

        int j = i >> 1;
        int o = i & 1;
        float* fa = (float*)&cb->A[j];
        fa[0 + o] = xf;
        fa[2 + o] = yf;
    }
}

extern "C" void kernel_launch(void* const* d_in, const int* in_sizes, int n_in,
                              void* d_out, int out_size) {
    const float* normals = (const float*)d_in[0];
    const int*   idxs    = (const int*)d_in[1];
    float*       out     = (float*)d_out;

    const int B = 8;
    int P = in_sizes[1];            // B*S = 32768
    int S = P / B;                  // 4096
    int N = in_sizes[0] / (B * 3);  // 500000

    int logS = -1;
    if (S > 0 && (S & (S - 1)) == 0) {
        logS = 0;
        while ((1 << logS) < S) logS++;
    }

    NPCodebook cb;
    np_build_codebook(&cb);

    // 2 lanes per point; single kernel, one balanced wave: 147 x 448
    long long total = 2LL * P;
    int blocks = (int)((total + TPB - 1) / TPB);
    if (out_size == 14 * P) {
        np_main_kernel<1><<<blocks, TPB>>>(cb, normals, idxs, out, N, S, logS, P);
    } else {
        np_main_kernel<0><<<blocks, TPB>>>(cb, normals, idxs, out, N, S, logS, P);
    }
}